// round 12
// baseline (speedup 1.0000x reference)
#include <cuda_runtime.h>
#include <cstddef>

#define Hd 10
#define Td 20
#define M1 5

using u64 = unsigned long long;

// ---- f32x2 packed helpers (sm_100+) ----
__device__ __forceinline__ u64 pack2(float lo, float hi) {
    u64 r; asm("mov.b64 %0, {%1, %2};" : "=l"(r) : "f"(lo), "f"(hi)); return r;
}
__device__ __forceinline__ void unpack2(u64 v, float &lo, float &hi) {
    asm("mov.b64 {%0, %1}, %2;" : "=f"(lo), "=f"(hi) : "l"(v));
}
__device__ __forceinline__ void fma2(u64 &d, u64 a, u64 b) {
    asm("fma.rn.f32x2 %0, %1, %2, %0;" : "+l"(d) : "l"(a), "l"(b));
}
__device__ __forceinline__ u64 fma2_3(u64 a, u64 b, u64 c) {
    u64 d; asm("fma.rn.f32x2 %0, %1, %2, %3;" : "=l"(d) : "l"(a), "l"(b), "l"(c)); return d;
}

// ---- activations ----
__device__ __forceinline__ float tanh_fast(float x) {
    float r; asm("tanh.approx.f32 %0, %1;" : "=f"(r) : "f"(x)); return r;
}
// sigmoid of 2y, where y = 0.5*x was accumulated (0.5 folded into weights)
__device__ __forceinline__ float sigp(float y) {
    return fmaf(tanh_fast(y), 0.5f, 0.5f);          // MUFU + FFMA
}
__device__ __forceinline__ float sig_acc(float x) {  // accurate, for final score
    return __fdividef(1.0f, 1.0f + __expf(-x));
}

__global__ void __launch_bounds__(256, 2)
lstm_disc_kernel(const float* __restrict__ values,
                 const float* __restrict__ masks,
                 const float* __restrict__ W_ih,   // (40,1)
                 const float* __restrict__ W_hh,   // (40,10) row-major
                 const float* __restrict__ b_ih,   // (40)
                 const float* __restrict__ b_hh,   // (40)
                 const float* __restrict__ W1,     // (5,10)
                 const float* __restrict__ b1,     // (5)
                 const float* __restrict__ W2,     // (1,5)
                 const float* __restrict__ b2,     // (1)
                 float* __restrict__ out,          // scores (B,T) then masks (B,T)
                 int B)
{
    // Lane-major gate weights, i/f/o pre-scaled by 0.5 (exact binary scaling):
    // sW[u][k] = float4{ 0.5*Wi[u][k], 0.5*Wf[u][k], Wg[u][k], 0.5*Wo[u][k] }
    __shared__ __align__(16) float sW[Hd][Hd][4];   // 1600 B
    __shared__ __align__(16) float sBias[Hd][4];    // scaled biases, order {i,f,g,o}
    __shared__ __align__(16) float sWx[Hd][4];      // scaled W_ih, order {i,f,g,o}
    __shared__ __align__(16) float sW1r[M1][12];    // W1 rows padded to 12 (3x float4)
    __shared__ float sB1[M1];
    __shared__ float sW2[M1];
    __shared__ float sB2;

    const int tid = threadIdx.x;
    for (int i = tid; i < Hd * Hd * 4; i += blockDim.x) {
        int u = i / 40, r = i % 40, k = r / 4, g = r % 4;
        float sc = (g == 2) ? 1.0f : 0.5f;
        sW[u][k][g] = sc * W_hh[(g * 10 + u) * Hd + k];
    }
    if (tid < Hd * 4) {
        int u = tid / 4, g = tid % 4;
        int j = g * 10 + u;
        float sc = (g == 2) ? 1.0f : 0.5f;
        sBias[u][g] = sc * (b_ih[j] + b_hh[j]);
        sWx[u][g]   = sc * W_ih[j];
    }
    if (tid < M1 * 12) {
        int j = tid / 12, k = tid % 12;
        sW1r[j][k] = (k < Hd) ? W1[j * Hd + k] : 0.0f;
    }
    if (tid < M1) { sB1[tid] = b1[tid]; sW2[tid] = W2[tid]; }
    if (tid == 0) sB2 = b2[0];
    __syncthreads();

    const int gtid = blockIdx.x * blockDim.x + tid;
    const int pr = gtid >> 1;            // pair index -> elements 2pr, 2pr+1
    const int q  = gtid & 1;             // which lane-half this thread owns
    const int ub = 5 * q;
    const int nthreads = gridDim.x * blockDim.x;

    const int e0 = 2 * pr, e1 = 2 * pr + 1;
    if (e1 < B) {
        const float* __restrict__ vr0 = values + (size_t)e0 * Td;
        const float* __restrict__ vr1 = values + (size_t)e1 * Td;
        float* __restrict__ sr0 = out + (size_t)e0 * Td;
        float* __restrict__ sr1 = out + (size_t)e1 * Td;

        float h0[Hd + 2], h1[Hd + 2], c0[5], c1[5];
#pragma unroll
        for (int k = 0; k < Hd + 2; k++) { h0[k] = 0.f; h1[k] = 0.f; }
#pragma unroll
        for (int k = 0; k < 5; k++) { c0[k] = 0.f; c1[k] = 0.f; }

#pragma unroll 1
        for (int t = 0; t < Td; t++) {
            // ---- MLP scoring head (pre-update h), rows split by parity ----
            float p0 = (q == 0) ? sB2 : 0.0f;
            float p1 = p0;
#pragma unroll
            for (int jj = 0; jj < 3; jj++) {
                const int j = 2 * jj + q;
                if (j < M1) {
                    const float4* __restrict__ wr = (const float4*)sW1r[j];
                    float z0 = sB1[j], z1 = z0;
#pragma unroll
                    for (int p4 = 0; p4 < 3; p4++) {
                        const float4 w = wr[p4];
                        z0 = fmaf(h0[4 * p4],     w.x, z0);
                        z0 = fmaf(h0[4 * p4 + 1], w.y, z0);
                        z0 = fmaf(h0[4 * p4 + 2], w.z, z0);
                        z0 = fmaf(h0[4 * p4 + 3], w.w, z0);
                        z1 = fmaf(h1[4 * p4],     w.x, z1);
                        z1 = fmaf(h1[4 * p4 + 1], w.y, z1);
                        z1 = fmaf(h1[4 * p4 + 2], w.z, z1);
                        z1 = fmaf(h1[4 * p4 + 3], w.w, z1);
                    }
                    z0 = fmaxf(z0, 0.2f * z0);       // leaky_relu(0.2)
                    z1 = fmaxf(z1, 0.2f * z1);
                    const float w2j = sW2[j];
                    p0 = fmaf(w2j, z0, p0);
                    p1 = fmaf(w2j, z1, p1);
                }
            }
            const float op0 = __shfl_xor_sync(0xffffffffu, p0, 1);
            const float op1 = __shfl_xor_sync(0xffffffffu, p1, 1);
            if (q == 0) sr0[t] = sig_acc(p0 + op0);
            else        sr1[t] = sig_acc(p1 + op1);

            // ---- LSTM gates: R9 memory pattern, f32x2 accumulators (i,f)/(g,o) ----
            const float x0 = vr0[t];
            const float x1 = vr1[t];
            const u64 x0d = pack2(x0, x0);
            const u64 x1d = pack2(x1, x1);
            float hn0[5], hn1[5];
#pragma unroll
            for (int l = 0; l < 5; l++) {
                const int u = ub + l;
                const float4 bi = *(const float4*)sBias[u];
                const float4 wx = *(const float4*)sWx[u];
                const u64 biIF = pack2(bi.x, bi.y), biGO = pack2(bi.z, bi.w);
                const u64 wxIF = pack2(wx.x, wx.y), wxGO = pack2(wx.z, wx.w);
                u64 aIF0 = fma2_3(x0d, wxIF, biIF);
                u64 aGO0 = fma2_3(x0d, wxGO, biGO);
                u64 aIF1 = fma2_3(x1d, wxIF, biIF);
                u64 aGO1 = fma2_3(x1d, wxGO, biGO);

                const float4* __restrict__ wrow = (const float4*)&sW[u][0][0];
#pragma unroll
                for (int k = 0; k < Hd; k++) {
                    const float4 w = wrow[k];           // LDS.128 (same as R9)
                    const u64 wIF = pack2(w.x, w.y);
                    const u64 wGO = pack2(w.z, w.w);
                    const u64 h0d = pack2(h0[k], h0[k]);
                    fma2(aIF0, h0d, wIF);
                    fma2(aGO0, h0d, wGO);
                    const u64 h1d = pack2(h1[k], h1[k]);
                    fma2(aIF1, h1d, wIF);
                    fma2(aGO1, h1d, wGO);
                }

                float aI0, aF0, aG0, aO0, aI1, aF1, aG1, aO1;
                unpack2(aIF0, aI0, aF0); unpack2(aGO0, aG0, aO0);
                unpack2(aIF1, aI1, aF1); unpack2(aGO1, aG1, aO1);

                const float cn0 = fmaf(sigp(aF0), c0[l], sigp(aI0) * tanh_fast(aG0));
                const float cn1 = fmaf(sigp(aF1), c1[l], sigp(aI1) * tanh_fast(aG1));
                c0[l] = cn0; c1[l] = cn1;
                hn0[l] = sigp(aO0) * tanh_fast(cn0);
                hn1[l] = sigp(aO1) * tanh_fast(cn1);
            }

            // ---- exchange h halves with partner thread (both elements) ----
#pragma unroll
            for (int i = 0; i < 5; i++) {
                const float v0 = __shfl_xor_sync(0xffffffffu, hn0[i], 1);
                const float v1 = __shfl_xor_sync(0xffffffffu, hn1[i], 1);
                h0[i]     = (q == 0) ? hn0[i] : v0;
                h0[5 + i] = (q == 0) ? v0 : hn0[i];
                h1[i]     = (q == 0) ? hn1[i] : v1;
                h1[5 + i] = (q == 0) ? v1 : hn1[i];
            }
        }
    }

    // ---- masks passthrough: coalesced grid-stride float4 copy ----
    {
        const float4* __restrict__ mi = (const float4*)masks;
        float4* __restrict__ mo = (float4*)(out + (size_t)B * Td);
        const int n4 = (B * Td) / 4;
#pragma unroll 1
        for (int i = gtid; i < n4; i += nthreads) mo[i] = mi[i];
    }
}

extern "C" void kernel_launch(void* const* d_in, const int* in_sizes, int n_in,
                              void* d_out, int out_size)
{
    const float* values = (const float*)d_in[0];
    const float* masks  = (const float*)d_in[1];
    const float* W_ih   = (const float*)d_in[2];
    const float* W_hh   = (const float*)d_in[3];
    const float* b_ih   = (const float*)d_in[4];
    const float* b_hh   = (const float*)d_in[5];
    const float* W1     = (const float*)d_in[6];
    const float* b1     = (const float*)d_in[7];
    const float* W2     = (const float*)d_in[8];
    const float* b2     = (const float*)d_in[9];

    const int BT = in_sizes[0];          // B*T
    const int B  = BT / Td;
    float* out = (float*)d_out;

    const int nthreads = B;              // 2 threads per 2 elements
    lstm_disc_kernel<<<(nthreads + 255) / 256, 256>>>(
        values, masks, W_ih, W_hh, b_ih, b_hh, W1, b1, W2, b2, out, B);
}